// round 12
// baseline (speedup 1.0000x reference)
#include <cuda_runtime.h>
#include <cuda_fp16.h>
#include <cstdint>

typedef unsigned long long ull;

#define NPG 9
#define EPG 36
#define NGRAPHS 100000
#define NPAIRS (NGRAPHS / 2)
#define NEDGES (NGRAPHS * EPG)
#define WARPS 16
#define THREADS (WARPS * 32)
#define GB 3                 // graph-PAIRS per warp batch
#define NBATCH ((NPAIRS + GB - 1) / GB)   // 16667 (last batch partial)
#define GRID 152
#define TOTW (GRID * WARPS)
#define FULLM 0xffffffffu

// ---- packed f32x2 helpers ----
__device__ __forceinline__ ull pack2(float a, float b) {
    ull r; asm("mov.b64 %0, {%1, %2};" : "=l"(r) : "f"(a), "f"(b)); return r;
}
__device__ __forceinline__ void unpack2(ull v, float& a, float& b) {
    asm("mov.b64 {%0, %1}, %2;" : "=f"(a), "=f"(b) : "l"(v));
}
__device__ __forceinline__ ull fma2(ull a, ull b, ull c) {
    ull d; asm("fma.rn.f32x2 %0, %1, %2, %3;" : "=l"(d) : "l"(a), "l"(b), "l"(c)); return d;
}
__device__ __forceinline__ ull add2(ull a, ull b) {
    ull d; asm("add.rn.f32x2 %0, %1, %2;" : "=l"(d) : "l"(a), "l"(b)); return d;
}
__device__ __forceinline__ ull dup2(float a) { return pack2(a, a); }
__device__ __forceinline__ ull relu2(ull v) {
    float a, b; unpack2(v, a, b);
    return pack2(fmaxf(a, 0.f), fmaxf(b, 0.f));
}
// half2 (g0,g1) -> packed "scaled f32x2" via pure ALU bit ops (NO F2F).
// Produces true_value * 2^-112 per component; the 2^112 is pre-folded into W2.
// Exact for normal halves; denormal halves (<6.1e-5) collapse to ~0 (noise).
__device__ __forceinline__ ull h2u_fast(unsigned v) {
    unsigned lo = (v << 13) & 0x0FFFE000u;
    unsigned hi = (v >> 3)  & 0x0FFFE000u;
    ull r; asm("mov.b64 %0, {%1, %2};" : "=l"(r) : "r"(lo), "r"(hi));
    return r;
}

// shared layout offsets (bytes)
#define OFF_FC1S  0        // [32][32] float4 interleaved station rows  16384 B
#define OFF_FC1C  16384    // [32][32] float4 interleaved ctx rows(/9)  16384 B
#define OFF_W2X   32768    // [8][64]  float4 interleaved (4ch/kc), x2^112  8192 B
#define OFF_W1X   40960    // [8][32]  float2 interleaved                2048 B
#define OFF_B1    43008    // 32 f32                                      128 B
#define OFF_B2    43136    // 64 f32                                      256 B
#define OFF_FB    43392    // 64 f32 (fc1b)                               256 B
#define OFF_F2    43648    // 64 f32 (fc2w)                               256 B
#define OFF_WS    43904

// per-warp scratch; f32x2 values interleaved as (graph0, graph1) pairs.
// H1 stored as half2 (g0,g1) per channel — halves the S5 broadcast bytes.
struct __align__(16) WS {
    ull      Xi[144];        // X pair [n][k]                1152 B
    ull      Apair[90];      // A pair [n][s], stride 10      720 B
    unsigned H1h[288];       // H1 half2 [n][c] (9*32)       1152 B
    ull      comb[GB * 192]; // st0/st8/ctx pairs            4608 B
};                           // 7632 B

__device__ int g_ctr;     // zero-initialized; reset by final-ticket warp each run

__global__ void __launch_bounds__(THREADS, 1) gqn_kernel(
    const float* __restrict__ x,
    const int*   __restrict__ esrc, const int* __restrict__ edst,
    const float* __restrict__ W1,  const float* __restrict__ b1,
    const float* __restrict__ W2,  const float* __restrict__ b2,
    const float* __restrict__ fc1w, const float* __restrict__ fc1b,
    const float* __restrict__ fc2w, const float* __restrict__ fc2b,
    float* __restrict__ out)
{
    extern __shared__ char smem[];
    float4* f4s = (float4*)(smem + OFF_FC1S);
    float4* f4c = (float4*)(smem + OFF_FC1C);
    float4* w2v = (float4*)(smem + OFF_W2X);
    float2* w1v = (float2*)(smem + OFF_W1X);
    float* cB1  = (float*)(smem + OFF_B1);
    float* cB2  = (float*)(smem + OFF_B2);
    float* cFB  = (float*)(smem + OFF_FB);
    float* cF2  = (float*)(smem + OFF_F2);
    WS* wsAll   = (WS*)(smem + OFF_WS);

    const int tid = threadIdx.x, warp = tid >> 5, lane = tid & 31;

    // ---- build interleaved weight layouts ----
    const float NINTH = 1.f / 9.f;
    const float SC112 = __uint_as_float(0x77800000u);   // 2^112
    for (int i = tid; i < 32 * 32; i += THREADS) {   // i = j2*32 + lane
        const int j2 = i >> 5, ln = i & 31;
        const int r0 = 2 * j2, r1 = 2 * j2 + 1;
        float4 v;
        v.x = fc1w[r0 * 64 + ln];      v.y = fc1w[r0 * 64 + 32 + ln];
        v.z = fc1w[r1 * 64 + ln];      v.w = fc1w[r1 * 64 + 32 + ln];
        f4s[i] = v;
        // ctx rows pre-scaled by 1/9 (mean-pool folded into weights)
        v.x = fc1w[(64 + r0) * 64 + ln] * NINTH; v.y = fc1w[(64 + r0) * 64 + 32 + ln] * NINTH;
        v.z = fc1w[(64 + r1) * 64 + ln] * NINTH; v.w = fc1w[(64 + r1) * 64 + 32 + ln] * NINTH;
        f4c[i] = v;
    }
    // W2 interleave, pre-scaled by 2^112 to undo the fp16 bit-expansion bias:
    //   w2v[kc*64 + 2*ln + h] = { W2[c][ln], W2[c][32+ln], W2[c+1][ln], W2[c+1][32+ln] }*2^112, c = 4kc+2h
    for (int i = tid; i < 8 * 64; i += THREADS) {
        const int kc = i >> 6, r = i & 63, ln = r >> 1, h = r & 1;
        const int c0 = 4 * kc + 2 * h;
        float4 v;
        v.x = W2[c0 * 64 + ln] * SC112;        v.y = W2[c0 * 64 + 32 + ln] * SC112;
        v.z = W2[(c0 + 1) * 64 + ln] * SC112;  v.w = W2[(c0 + 1) * 64 + 32 + ln] * SC112;
        w2v[i] = v;
    }
    for (int i = tid; i < 8 * 32; i += THREADS) {
        const int k2 = i >> 5, ln = i & 31;
        float2 v;
        v.x = W1[(2 * k2) * 32 + ln]; v.y = W1[(2 * k2 + 1) * 32 + ln];
        w1v[i] = v;
    }
    if (tid < 32)                    cB1[tid] = b1[tid];
    else if (tid < 96)               cB2[tid - 32] = b2[tid - 32];
    else if (tid < 160)              cFB[tid - 96] = fc1b[tid - 96];
    else if (tid < 224)              cF2[tid - 160] = fc2w[tid - 160];

    const float fc2bias = fc2b[0];

    WS& ws = wsAll[warp];
    __syncthreads();

    // ---- grab first batch ----
    int cur = 0;
    if (lane == 0) cur = atomicAdd(&g_ctr, 1);
    cur = __shfl_sync(FULLM, cur, 0);

    // ---- prefetch edges for first pair of first batch ----
    int ps0, ps1, ps2 = 0, pd0, pd1, pd2 = 0;
    {
        int pf = (cur < NBATCH) ? cur * GB : 0;
        const int* eb = esrc + (size_t)pf * 72;
        const int* db = edst + (size_t)pf * 72;
        ps0 = eb[lane]; ps1 = eb[32 + lane];
        pd0 = db[lane]; pd1 = db[32 + lane];
        if (lane < 8) { ps2 = eb[64 + lane]; pd2 = db[64 + lane]; }
    }

    while (cur < NBATCH) {
        // grab next batch early; latency hidden under batch work
        int nxt = 0;
        if (lane == 0) nxt = atomicAdd(&g_ctr, 1);
        nxt = __shfl_sync(FULLM, nxt, 0);

        const int base = cur * GB;

        #pragma unroll 1
        for (int pi = 0; pi < GB; ++pi) {
            const int p = base + pi;
            if (p >= NPAIRS) break;

            // ---- issue X LDGs for this pair (consumed much later) ----
            const float4* xv = (const float4*)(x + (size_t)p * 288);
            float4 xa = xv[lane], xb = xv[36 + lane];
            float4 xc, xd;
            if (lane < 4) { xc = xv[32 + lane]; xd = xv[68 + lane]; }

            // ---- consume prefetched edges; prefetch next pair's edges ----
            const int cs0 = ps0, cs1 = ps1, cs2 = ps2;
            const int cd0 = pd0, cd1 = pd1, cd2 = pd2;
            {
                int np;
                if (pi == GB - 1) np = (nxt < NBATCH) ? nxt * GB : 0;
                else              np = (p + 1 < NPAIRS) ? p + 1 : ((nxt < NBATCH) ? nxt * GB : 0);
                const int* eb = esrc + (size_t)np * 72;
                const int* db = edst + (size_t)np * 72;
                ps0 = eb[lane]; ps1 = eb[32 + lane];
                pd0 = db[lane]; pd1 = db[32 + lane];
                if (lane < 8) { ps2 = eb[64 + lane]; pd2 = db[64 + lane]; }
            }

            // ---- zero Apair ----
            {
                ulonglong2 z2 = make_ulonglong2(0ull, 0ull);
                *(ulonglong2*)&ws.Apair[2 * lane] = z2;
                if (lane < 13) *(ulonglong2*)&ws.Apair[64 + 2 * lane] = z2;
            }

            // ---- S2: adjacency via ballots/shuffles, 72 edges in 3 slots ----
            const int b0 = p * 18;              // node base of graph 2p
            const int sA = cs0 - b0, dA = cd0 - b0;
            const int obB = (lane < 4) ? 0 : 9;
            const int sB = cs1 - (b0 + obB);
            const int dB = cd1 - (b0 + obB);
            const int sC = (lane < 8) ? (cs2 - (b0 + 9)) : 15;
            const int dC = (lane < 8) ? (cd2 - (b0 + 9)) : 15;

            int myDeg = 1;                       // self-loop
            #pragma unroll
            for (int n = 0; n < 9; ++n) {
                unsigned bA = __ballot_sync(FULLM, dA == n);
                unsigned bB = __ballot_sync(FULLM, dB == n);
                unsigned bC = __ballot_sync(FULLM, dC == n);
                int c0 = __popc(bA) + __popc(bB & 0xFu);
                int c1 = __popc(bB & ~0xFu) + __popc(bC);
                if ((int)lane == n)      myDeg += c0;
                if ((int)lane == 16 + n) myDeg += c1;
            }
            const float di  = rsqrtf((float)myDeg);   // lanes 0-8: g0, 16-24: g1
            const float di2 = di * di;

            const float nA = __shfl_sync(FULLM, di, sA) * __shfl_sync(FULLM, di, dA);
            const int ob16 = (lane < 4) ? 0 : 16;
            const float nB = __shfl_sync(FULLM, di, sB + ob16) * __shfl_sync(FULLM, di, dB + ob16);
            const float nC = __shfl_sync(FULLM, di, sC + 16) * __shfl_sync(FULLM, di, dC + 16);

            const unsigned mA = __match_any_sync(FULLM, dA * 16 + sA);
            const unsigned mB = __match_any_sync(FULLM, ob16 * 256 + dB * 16 + sB);
            const unsigned kC = (lane < 8) ? (unsigned)(dC * 16 + sC) : (4096u + lane);
            const unsigned mC = __match_any_sync(FULLM, kC);

            __syncwarp();   // zeros visible
            if ((int)lane == __ffs(mA) - 1) {
                float* sl = (float*)&ws.Apair[dA * 10 + sA];
                sl[0] += (float)__popc(mA) * nA;
            }
            if (lane < 8 && (int)lane == __ffs(mC) - 1) {
                float* sl = (float*)&ws.Apair[dC * 10 + sC];
                sl[1] += (float)__popc(mC) * nC;
            }
            __syncwarp();
            if ((int)lane == __ffs(mB) - 1) {
                float* sl = (float*)&ws.Apair[dB * 10 + sB];
                sl[(lane < 4) ? 0 : 1] += (float)__popc(mB) * nB;
            }
            __syncwarp();
            if (lane < 9)
                ((float*)&ws.Apair[lane * 10 + lane])[0] += di2;
            if (lane >= 16 && lane < 25)
                ((float*)&ws.Apair[(lane - 16) * 10 + (lane - 16)])[1] += di2;

            // ---- S1b: store X pairs (LDG data now long arrived) ----
            {
                ulonglong2 u0 = { pack2(xa.x, xb.x), pack2(xa.y, xb.y) };
                ulonglong2 u1 = { pack2(xa.z, xb.z), pack2(xa.w, xb.w) };
                *(ulonglong2*)&ws.Xi[4 * lane]     = u0;
                *(ulonglong2*)&ws.Xi[4 * lane + 2] = u1;
                if (lane < 4) {
                    ulonglong2 v0 = { pack2(xc.x, xd.x), pack2(xc.y, xd.y) };
                    ulonglong2 v1 = { pack2(xc.z, xd.z), pack2(xc.w, xd.w) };
                    *(ulonglong2*)&ws.Xi[128 + 4 * lane] = v0;
                    *(ulonglong2*)&ws.Xi[130 + 4 * lane] = v1;
                }
            }
            __syncwarp();

            // ---- S3: Y = X @ W1 (k-outer, W1 via one LDS.64/iter) ----
            ull y[9];
            #pragma unroll
            for (int n = 0; n < 9; ++n) y[n] = 0ull;
            #pragma unroll
            for (int k2 = 0; k2 < 8; ++k2) {
                const float2 wv = w1v[k2 * 32 + lane];
                const ull w0 = dup2(wv.x);
                const ull w1 = dup2(wv.y);
                #pragma unroll
                for (int n = 0; n < 9; ++n) {
                    ulonglong2 xp = *(const ulonglong2*)&ws.Xi[n * 16 + 2 * k2];
                    y[n] = fma2(xp.x, w0, y[n]);
                    y[n] = fma2(xp.y, w1, y[n]);
                }
            }

            // ---- S4: H1 = relu(A@Y + b1), stored as half2 (g0,g1) ----
            {
                const ull b1d = dup2(cB1[lane]);
                #pragma unroll
                for (int n = 0; n < 9; ++n) {
                    const ulonglong2* ar = (const ulonglong2*)&ws.Apair[n * 10];
                    ull acc = b1d;
                    #pragma unroll
                    for (int sp = 0; sp < 4; ++sp) {
                        ulonglong2 av = ar[sp];
                        acc = fma2(av.x, y[2 * sp],     acc);
                        acc = fma2(av.y, y[2 * sp + 1], acc);
                    }
                    acc = fma2(ws.Apair[n * 10 + 8], y[8], acc);
                    float a, b; unpack2(acc, a, b);
                    __half2 h = __floats2half2_rn(fmaxf(a, 0.f), fmaxf(b, 0.f));
                    ws.H1h[n * 32 + lane] = *reinterpret_cast<unsigned*>(&h);
                }
            }
            __syncwarp();

            // ---- S5: G = H1 @ W2 — 4 channels per broadcast LDS.128,
            //      fp16 expanded with pure ALU bit ops (scale folded into W2) ----
            ull gl[9], gh[9];
            #pragma unroll
            for (int n = 0; n < 9; ++n) { gl[n] = 0ull; gh[n] = 0ull; }
            #pragma unroll
            for (int kc = 0; kc < 8; ++kc) {
                const float4 wva = w2v[kc * 64 + 2 * lane];
                const float4 wvb = w2v[kc * 64 + 2 * lane + 1];
                const ull w0l = dup2(wva.x), w0h = dup2(wva.y);
                const ull w1l = dup2(wva.z), w1h = dup2(wva.w);
                const ull w2l = dup2(wvb.x), w2h = dup2(wvb.y);
                const ull w3l = dup2(wvb.z), w3h = dup2(wvb.w);
                #pragma unroll
                for (int n = 0; n < 9; ++n) {
                    uint4 q = *(const uint4*)&ws.H1h[n * 32 + 4 * kc];
                    const ull h0 = h2u_fast(q.x);
                    gl[n] = fma2(h0, w0l, gl[n]); gh[n] = fma2(h0, w0h, gh[n]);
                    const ull h1 = h2u_fast(q.y);
                    gl[n] = fma2(h1, w1l, gl[n]); gh[n] = fma2(h1, w1h, gh[n]);
                    const ull h2 = h2u_fast(q.z);
                    gl[n] = fma2(h2, w2l, gl[n]); gh[n] = fma2(h2, w2h, gh[n]);
                    const ull h3 = h2u_fast(q.w);
                    gl[n] = fma2(h3, w3l, gl[n]); gh[n] = fma2(h3, w3h, gh[n]);
                }
            }

            // ---- S6: H2 = relu(A@G + b2); ctx SUM (1/9 folded into fc1c) + stations ----
            {
                const ull b2dl = dup2(cB2[lane]);
                const ull b2dh = dup2(cB2[lane + 32]);
                ull ctxl = 0ull, ctxh = 0ull, st0l = 0ull, st0h = 0ull, st8l = 0ull, st8h = 0ull;
                #pragma unroll
                for (int n = 0; n < 9; ++n) {
                    const ulonglong2* ar = (const ulonglong2*)&ws.Apair[n * 10];
                    ull al = b2dl, ah = b2dh;
                    #pragma unroll
                    for (int sp = 0; sp < 4; ++sp) {
                        ulonglong2 av = ar[sp];
                        al = fma2(av.x, gl[2 * sp],     al); ah = fma2(av.x, gh[2 * sp],     ah);
                        al = fma2(av.y, gl[2 * sp + 1], al); ah = fma2(av.y, gh[2 * sp + 1], ah);
                    }
                    const ull av8 = ws.Apair[n * 10 + 8];
                    al = fma2(av8, gl[8], al); ah = fma2(av8, gh[8], ah);
                    al = relu2(al); ah = relu2(ah);
                    ctxl = add2(ctxl, al); ctxh = add2(ctxh, ah);
                    if (n == 0) { st0l = al; st0h = ah; }
                    if (n == 8) { st8l = al; st8h = ah; }
                }

                ull* cb = &ws.comb[pi * 192];
                cb[lane]       = st0l; cb[32 + lane]  = st0h;
                cb[64 + lane]  = st8l; cb[96 + lane]  = st8h;
                cb[128 + lane] = ctxl; cb[160 + lane] = ctxh;
            }
        }
        __syncwarp();

        // ---- S7: FC head, batched over GB pairs (fc1 via 2 LDS.128/iter) ----
        ull zc[GB][2], q0a[GB][2], q1a[GB][2];
        {
            const ull fbl = dup2(cFB[lane]);
            const ull fbh = dup2(cFB[lane + 32]);
            #pragma unroll
            for (int pq = 0; pq < GB; ++pq) {
                zc[pq][0] = 0ull; zc[pq][1] = 0ull;
                q0a[pq][0] = fbl; q0a[pq][1] = fbh;
                q1a[pq][0] = fbl; q1a[pq][1] = fbh;
            }
        }
        #pragma unroll 4
        for (int j2 = 0; j2 < 32; ++j2) {
            const float4 wsv = f4s[j2 * 32 + lane];
            const float4 wcv = f4c[j2 * 32 + lane];
            const ull s0l = dup2(wsv.x), s0h = dup2(wsv.y);
            const ull s1l = dup2(wsv.z), s1h = dup2(wsv.w);
            const ull c0l = dup2(wcv.x), c0h = dup2(wcv.y);
            const ull c1l = dup2(wcv.z), c1h = dup2(wcv.w);
            #pragma unroll
            for (int pq = 0; pq < GB; ++pq) {
                const ull* cb = &ws.comb[pq * 192];
                ulonglong2 v0 = *(const ulonglong2*)&cb[2 * j2];
                ulonglong2 v1 = *(const ulonglong2*)&cb[64 + 2 * j2];
                ulonglong2 vc = *(const ulonglong2*)&cb[128 + 2 * j2];
                q0a[pq][0] = fma2(v0.x, s0l, q0a[pq][0]); q0a[pq][1] = fma2(v0.x, s0h, q0a[pq][1]);
                q0a[pq][0] = fma2(v0.y, s1l, q0a[pq][0]); q0a[pq][1] = fma2(v0.y, s1h, q0a[pq][1]);
                q1a[pq][0] = fma2(v1.x, s0l, q1a[pq][0]); q1a[pq][1] = fma2(v1.x, s0h, q1a[pq][1]);
                q1a[pq][0] = fma2(v1.y, s1l, q1a[pq][0]); q1a[pq][1] = fma2(v1.y, s1h, q1a[pq][1]);
                zc[pq][0]  = fma2(vc.x, c0l, zc[pq][0]);  zc[pq][1]  = fma2(vc.x, c0h, zc[pq][1]);
                zc[pq][0]  = fma2(vc.y, c1l, zc[pq][0]);  zc[pq][1]  = fma2(vc.y, c1h, zc[pq][1]);
            }
        }

        // ---- epilogue: relu, fc2 dot, warp reduce, store ----
        {
            const ull f2cl = dup2(cF2[lane]);
            const ull f2ch = dup2(cF2[lane + 32]);
            #pragma unroll
            for (int pq = 0; pq < GB; ++pq) {
                const int P = base + pq;
                #pragma unroll
                for (int v = 0; v < 2; ++v) {
                    ull zl = add2(zc[pq][0], v ? q1a[pq][0] : q0a[pq][0]);
                    ull zh = add2(zc[pq][1], v ? q1a[pq][1] : q0a[pq][1]);
                    zl = relu2(zl); zh = relu2(zh);
                    ull qp = fma2(zl, f2cl, 0ull);
                    qp = fma2(zh, f2ch, qp);
                    float qa, qb; unpack2(qp, qa, qb);
                    #pragma unroll
                    for (int off = 16; off; off >>= 1) {
                        qa += __shfl_xor_sync(FULLM, qa, off);
                        qb += __shfl_xor_sync(FULLM, qb, off);
                    }
                    if (lane == 0 && P < NPAIRS) {
                        out[4 * P + v]     = qa + fc2bias;
                        out[4 * P + 2 + v] = qb + fc2bias;
                    }
                }
            }
        }

        cur = nxt;
    }

    // final-ticket warp resets the counter for the next (graph-replayed) launch.
    // Total draws are exactly NBATCH+TOTW (atomic total order), so the warp that
    // drew value NBATCH+TOTW-1 executes this strictly after every other draw.
    if (lane == 0 && cur == NBATCH + TOTW - 1) atomicExch(&g_ctr, 0);
}

extern "C" void kernel_launch(void* const* d_in, const int* in_sizes, int n_in,
                              void* d_out, int out_size) {
    const float* x    = (const float*)d_in[0];
    const int*   ei   = (const int*)  d_in[1];
    const float* W1   = (const float*)d_in[3];
    const float* b1   = (const float*)d_in[4];
    const float* W2   = (const float*)d_in[5];
    const float* b2   = (const float*)d_in[6];
    const float* fc1w = (const float*)d_in[7];
    const float* fc1b = (const float*)d_in[8];
    const float* fc2w = (const float*)d_in[9];
    const float* fc2b = (const float*)d_in[10];

    const size_t shmem = OFF_WS + sizeof(WS) * WARPS;   // 166016 B
    cudaFuncSetAttribute(gqn_kernel, cudaFuncAttributeMaxDynamicSharedMemorySize, (int)shmem);
    gqn_kernel<<<GRID, THREADS, shmem>>>(x, ei, ei + NEDGES,
                                         W1, b1, W2, b2, fc1w, fc1b, fc2w, fc2b,
                                         (float*)d_out);
}

// round 13
// speedup vs baseline: 1.0628x; 1.0628x over previous
#include <cuda_runtime.h>
#include <cstdint>

typedef unsigned long long ull;

#define NPG 9
#define EPG 36
#define NGRAPHS 100000
#define NPAIRS (NGRAPHS / 2)
#define NEDGES (NGRAPHS * EPG)
#define WARPS 16
#define THREADS (WARPS * 32)
#define GB 3                 // graph-PAIRS per warp batch
#define NBATCH ((NPAIRS + GB - 1) / GB)   // 16667 (last batch partial)
#define GRID 152
#define TOTW (GRID * WARPS)
#define FULLM 0xffffffffu

// ---- packed f32x2 helpers ----
__device__ __forceinline__ ull pack2(float a, float b) {
    ull r; asm("mov.b64 %0, {%1, %2};" : "=l"(r) : "f"(a), "f"(b)); return r;
}
__device__ __forceinline__ void unpack2(ull v, float& a, float& b) {
    asm("mov.b64 {%0, %1}, %2;" : "=f"(a), "=f"(b) : "l"(v));
}
__device__ __forceinline__ ull fma2(ull a, ull b, ull c) {
    ull d; asm("fma.rn.f32x2 %0, %1, %2, %3;" : "=l"(d) : "l"(a), "l"(b), "l"(c)); return d;
}
__device__ __forceinline__ ull add2(ull a, ull b) {
    ull d; asm("add.rn.f32x2 %0, %1, %2;" : "=l"(d) : "l"(a), "l"(b)); return d;
}
__device__ __forceinline__ ull dup2(float a) { return pack2(a, a); }
__device__ __forceinline__ ull relu2(ull v) {
    float a, b; unpack2(v, a, b);
    return pack2(fmaxf(a, 0.f), fmaxf(b, 0.f));
}

// shared layout offsets (bytes) — W1X is 2048 B (8*32 float2)
#define OFF_FC1S  0        // [32][32] float4 interleaved station rows  16384 B
#define OFF_FC1C  16384    // [32][32] float4 interleaved ctx rows(/9)  16384 B
#define OFF_W2X   32768    // [16][32] float4 interleaved                8192 B
#define OFF_W1X   40960    // [8][32]  float2 interleaved                2048 B
#define OFF_B1    43008    // 32 f32                                      128 B
#define OFF_B2    43136    // 64 f32                                      256 B
#define OFF_FB    43392    // 64 f32 (fc1b)                               256 B
#define OFF_F2    43648    // 64 f32 (fc2w)                               256 B
#define OFF_WS    43904

// per-warp scratch; all f32x2 values interleaved as (graph0, graph1) pairs
struct __align__(16) WS {
    ull   Xi[144];        // X pair [n][k]                1152 B
    ull   Apair[90];      // A pair [n][s], stride 10      720 B
    ull   Qi[288];        // Q = A@H1 pair [n][c]         2304 B
    ull   comb[GB * 192]; // st0/st8/ctx pairs            4608 B
};

__device__ int g_ctr;     // zero-initialized; reset by final-ticket warp each run

__global__ void __launch_bounds__(THREADS, 1) gqn_kernel(
    const float* __restrict__ x,
    const int*   __restrict__ esrc, const int* __restrict__ edst,
    const float* __restrict__ W1,  const float* __restrict__ b1,
    const float* __restrict__ W2,  const float* __restrict__ b2,
    const float* __restrict__ fc1w, const float* __restrict__ fc1b,
    const float* __restrict__ fc2w, const float* __restrict__ fc2b,
    float* __restrict__ out)
{
    extern __shared__ char smem[];
    float4* f4s = (float4*)(smem + OFF_FC1S);
    float4* f4c = (float4*)(smem + OFF_FC1C);
    float4* w2v = (float4*)(smem + OFF_W2X);
    float2* w1v = (float2*)(smem + OFF_W1X);
    float* cB1  = (float*)(smem + OFF_B1);
    float* cB2  = (float*)(smem + OFF_B2);
    float* cFB  = (float*)(smem + OFF_FB);
    float* cF2  = (float*)(smem + OFF_F2);
    WS* wsAll   = (WS*)(smem + OFF_WS);

    const int tid = threadIdx.x, warp = tid >> 5, lane = tid & 31;

    // ---- build interleaved weight layouts (one LDS.128 per lane per iter) ----
    const float NINTH = 1.f / 9.f;
    for (int i = tid; i < 32 * 32; i += THREADS) {   // i = j2*32 + lane
        const int j2 = i >> 5, ln = i & 31;
        const int r0 = 2 * j2, r1 = 2 * j2 + 1;
        float4 v;
        v.x = fc1w[r0 * 64 + ln];      v.y = fc1w[r0 * 64 + 32 + ln];
        v.z = fc1w[r1 * 64 + ln];      v.w = fc1w[r1 * 64 + 32 + ln];
        f4s[i] = v;
        // ctx rows pre-scaled by 1/9 (mean-pool folded into weights)
        v.x = fc1w[(64 + r0) * 64 + ln] * NINTH; v.y = fc1w[(64 + r0) * 64 + 32 + ln] * NINTH;
        v.z = fc1w[(64 + r1) * 64 + ln] * NINTH; v.w = fc1w[(64 + r1) * 64 + 32 + ln] * NINTH;
        f4c[i] = v;
    }
    for (int i = tid; i < 16 * 32; i += THREADS) {   // i = k2*32 + lane
        const int k2 = i >> 5, ln = i & 31;
        float4 v;
        v.x = W2[(2 * k2) * 64 + ln];     v.y = W2[(2 * k2) * 64 + 32 + ln];
        v.z = W2[(2 * k2 + 1) * 64 + ln]; v.w = W2[(2 * k2 + 1) * 64 + 32 + ln];
        w2v[i] = v;
    }
    for (int i = tid; i < 8 * 32; i += THREADS) {
        const int k2 = i >> 5, ln = i & 31;
        float2 v;
        v.x = W1[(2 * k2) * 32 + ln]; v.y = W1[(2 * k2 + 1) * 32 + ln];
        w1v[i] = v;
    }
    if (tid < 32)                    cB1[tid] = b1[tid];
    else if (tid < 96)               cB2[tid - 32] = b2[tid - 32];
    else if (tid < 160)              cFB[tid - 96] = fc1b[tid - 96];
    else if (tid < 224)              cF2[tid - 160] = fc2w[tid - 160];

    const float fc2bias = fc2b[0];

    WS& ws = wsAll[warp];
    __syncthreads();

    // ---- grab first batch ----
    int cur = 0;
    if (lane == 0) cur = atomicAdd(&g_ctr, 1);
    cur = __shfl_sync(FULLM, cur, 0);

    // ---- prefetch edges for first pair of first batch ----
    int ps0, ps1, ps2 = 0, pd0, pd1, pd2 = 0;
    {
        int pf = (cur < NBATCH) ? cur * GB : 0;
        const int* eb = esrc + (size_t)pf * 72;
        const int* db = edst + (size_t)pf * 72;
        ps0 = eb[lane]; ps1 = eb[32 + lane];
        pd0 = db[lane]; pd1 = db[32 + lane];
        if (lane < 8) { ps2 = eb[64 + lane]; pd2 = db[64 + lane]; }
    }

    while (cur < NBATCH) {
        // grab next batch early; latency hidden under batch work
        int nxt = 0;
        if (lane == 0) nxt = atomicAdd(&g_ctr, 1);
        nxt = __shfl_sync(FULLM, nxt, 0);

        const int base = cur * GB;

        #pragma unroll 1
        for (int pi = 0; pi < GB; ++pi) {
            const int p = base + pi;
            if (p >= NPAIRS) break;

            // ---- issue X LDGs for this pair (consumed much later) ----
            const float4* xv = (const float4*)(x + (size_t)p * 288);
            float4 xa = xv[lane], xb = xv[36 + lane];
            float4 xc, xd;
            if (lane < 4) { xc = xv[32 + lane]; xd = xv[68 + lane]; }

            // ---- consume prefetched edges; prefetch next pair's edges ----
            const int cs0 = ps0, cs1 = ps1, cs2 = ps2;
            const int cd0 = pd0, cd1 = pd1, cd2 = pd2;
            {
                int np;
                if (pi == GB - 1) np = (nxt < NBATCH) ? nxt * GB : 0;
                else              np = (p + 1 < NPAIRS) ? p + 1 : ((nxt < NBATCH) ? nxt * GB : 0);
                const int* eb = esrc + (size_t)np * 72;
                const int* db = edst + (size_t)np * 72;
                ps0 = eb[lane]; ps1 = eb[32 + lane];
                pd0 = db[lane]; pd1 = db[32 + lane];
                if (lane < 8) { ps2 = eb[64 + lane]; pd2 = db[64 + lane]; }
            }

            // ---- S2a: register-only adjacency math (ballots, norms, matches) ----
            const int b0 = p * 18;              // node base of graph 2p
            const int sA = cs0 - b0, dA = cd0 - b0;
            const int obB = (lane < 4) ? 0 : 9;
            const int sB = cs1 - (b0 + obB);
            const int dB = cd1 - (b0 + obB);
            const int sC = (lane < 8) ? (cs2 - (b0 + 9)) : 15;
            const int dC = (lane < 8) ? (cd2 - (b0 + 9)) : 15;

            int myDeg = 1;                       // self-loop
            #pragma unroll
            for (int n = 0; n < 9; ++n) {
                unsigned bA = __ballot_sync(FULLM, dA == n);
                unsigned bB = __ballot_sync(FULLM, dB == n);
                unsigned bC = __ballot_sync(FULLM, dC == n);
                int c0 = __popc(bA) + __popc(bB & 0xFu);
                int c1 = __popc(bB & ~0xFu) + __popc(bC);
                if ((int)lane == n)      myDeg += c0;
                if ((int)lane == 16 + n) myDeg += c1;
            }
            const float di  = rsqrtf((float)myDeg);   // lanes 0-8: g0, 16-24: g1
            const float di2 = di * di;

            const float nA = __shfl_sync(FULLM, di, sA) * __shfl_sync(FULLM, di, dA);
            const int ob16 = (lane < 4) ? 0 : 16;
            const float nB = __shfl_sync(FULLM, di, sB + ob16) * __shfl_sync(FULLM, di, dB + ob16);
            const float nC = __shfl_sync(FULLM, di, sC + 16) * __shfl_sync(FULLM, di, dC + 16);

            const unsigned mA = __match_any_sync(FULLM, dA * 16 + sA);
            const unsigned mB = __match_any_sync(FULLM, ob16 * 256 + dB * 16 + sB);
            const unsigned kC = (lane < 8) ? (unsigned)(dC * 16 + sC) : (4096u + lane);
            const unsigned mC = __match_any_sync(FULLM, kC);

            // ---- S2b: zero Apair with diagonal (di2) folded in ----
            {
                // region1: ulls 2*lane, 2*lane+1; diag ulls 11n (n<=5) here
                const int cA1 = 2 * lane, cB1x = cA1 + 1;
                const int nA1 = cA1 / 11, nB1 = cB1x / 11;
                const bool dgA = (nA1 * 11 == cA1) && (cA1 <= 55);
                const bool dgB = (nB1 * 11 == cB1x) && (cB1x <= 55);
                int nn = dgB ? nB1 : nA1; if (nn > 8) nn = 8;
                float va = __shfl_sync(FULLM, di2, nn);
                float vb = __shfl_sync(FULLM, di2, 16 + nn);
                ull dv = pack2(va, vb);
                ulonglong2 z;
                z.x = dgA ? dv : 0ull;
                z.y = dgB ? dv : 0ull;
                *(ulonglong2*)&ws.Apair[2 * lane] = z;

                // region2: ulls 64+2*lane (lane<13); diag ulls 66,77,88 (n=6,7,8)
                const int cC1 = 64 + 2 * lane, cD1 = cC1 + 1;
                const int nC1 = cC1 / 11, nD1 = cD1 / 11;
                const bool dgC = (nC1 * 11 == cC1) && (cC1 >= 66) && (cC1 <= 88);
                const bool dgD = (nD1 * 11 == cD1) && (cD1 >= 66) && (cD1 <= 88);
                int nn2 = dgD ? nD1 : nC1; if (nn2 > 8) nn2 = 8; if (nn2 < 0) nn2 = 0;
                float vc = __shfl_sync(FULLM, di2, nn2);
                float vd = __shfl_sync(FULLM, di2, 16 + nn2);
                ull dv2 = pack2(vc, vd);
                if (lane < 13) {
                    ulonglong2 z2;
                    z2.x = dgC ? dv2 : 0ull;
                    z2.y = dgD ? dv2 : 0ull;
                    *(ulonglong2*)&ws.Apair[64 + 2 * lane] = z2;
                }
            }
            __syncwarp();   // zeros+diag visible

            // ---- S2c: phase 1 leader adds (slots A and C) ----
            if ((int)lane == __ffs(mA) - 1) {
                float* sl = (float*)&ws.Apair[dA * 10 + sA];
                sl[0] += (float)__popc(mA) * nA;
            }
            if (lane < 8 && (int)lane == __ffs(mC) - 1) {
                float* sl = (float*)&ws.Apair[dC * 10 + sC];
                sl[1] += (float)__popc(mC) * nC;
            }
            __syncwarp();

            // ---- S2d: phase 2 leader adds (slot B) + S1b Xi stores ----
            if ((int)lane == __ffs(mB) - 1) {
                float* sl = (float*)&ws.Apair[dB * 10 + sB];
                sl[(lane < 4) ? 0 : 1] += (float)__popc(mB) * nB;
            }
            {
                ulonglong2 u0 = { pack2(xa.x, xb.x), pack2(xa.y, xb.y) };
                ulonglong2 u1 = { pack2(xa.z, xb.z), pack2(xa.w, xb.w) };
                *(ulonglong2*)&ws.Xi[4 * lane]     = u0;
                *(ulonglong2*)&ws.Xi[4 * lane + 2] = u1;
                if (lane < 4) {
                    ulonglong2 v0 = { pack2(xc.x, xd.x), pack2(xc.y, xd.y) };
                    ulonglong2 v1 = { pack2(xc.z, xd.z), pack2(xc.w, xd.w) };
                    *(ulonglong2*)&ws.Xi[128 + 4 * lane] = v0;
                    *(ulonglong2*)&ws.Xi[130 + 4 * lane] = v1;
                }
            }
            __syncwarp();

            // ---- S3: Y = X @ W1 (k-outer, W1 via one LDS.64/iter) ----
            ull y[9];
            #pragma unroll
            for (int n = 0; n < 9; ++n) y[n] = 0ull;
            #pragma unroll
            for (int k2 = 0; k2 < 8; ++k2) {
                const float2 wv = w1v[k2 * 32 + lane];
                const ull w0 = dup2(wv.x);
                const ull w1 = dup2(wv.y);
                #pragma unroll
                for (int n = 0; n < 9; ++n) {
                    ulonglong2 xp = *(const ulonglong2*)&ws.Xi[n * 16 + 2 * k2];
                    y[n] = fma2(xp.x, w0, y[n]);
                    y[n] = fma2(xp.y, w1, y[n]);
                }
            }

            // ---- S4: H1 = relu(A@Y + b1) — kept in registers ----
            ull h1[9];
            {
                const ull b1d = dup2(cB1[lane]);
                #pragma unroll
                for (int n = 0; n < 9; ++n) {
                    const ulonglong2* ar = (const ulonglong2*)&ws.Apair[n * 10];
                    ull acc = b1d;
                    #pragma unroll
                    for (int sp = 0; sp < 4; ++sp) {
                        ulonglong2 av = ar[sp];
                        acc = fma2(av.x, y[2 * sp],     acc);
                        acc = fma2(av.y, y[2 * sp + 1], acc);
                    }
                    acc = fma2(ws.Apair[n * 10 + 8], y[8], acc);
                    h1[n] = relu2(acc);
                }
            }

            // ---- S4b: Q = A @ H1 (in-register mix), staged to shared ----
            #pragma unroll
            for (int n = 0; n < 9; ++n) {
                const ulonglong2* ar = (const ulonglong2*)&ws.Apair[n * 10];
                ull acc = 0ull;
                #pragma unroll
                for (int sp = 0; sp < 4; ++sp) {
                    ulonglong2 av = ar[sp];
                    acc = fma2(av.x, h1[2 * sp],     acc);
                    acc = fma2(av.y, h1[2 * sp + 1], acc);
                }
                acc = fma2(ws.Apair[n * 10 + 8], h1[8], acc);
                ws.Qi[n * 32 + lane] = acc;
            }
            __syncwarp();

            // ---- S5: H2 = relu(Q @ W2 + b2) directly; extract ctx/st0/st8 ----
            {
                ull gl[9], gh[9];
                const ull b2dl = dup2(cB2[lane]);
                const ull b2dh = dup2(cB2[lane + 32]);
                #pragma unroll
                for (int n = 0; n < 9; ++n) { gl[n] = b2dl; gh[n] = b2dh; }
                #pragma unroll
                for (int k2 = 0; k2 < 16; ++k2) {
                    const float4 wv = w2v[k2 * 32 + lane];
                    const ull w0l = dup2(wv.x);
                    const ull w0h = dup2(wv.y);
                    const ull w1l = dup2(wv.z);
                    const ull w1h = dup2(wv.w);
                    #pragma unroll
                    for (int n = 0; n < 9; ++n) {
                        ulonglong2 hv = *(const ulonglong2*)&ws.Qi[n * 32 + 2 * k2];
                        gl[n] = fma2(hv.x, w0l, gl[n]); gh[n] = fma2(hv.x, w0h, gh[n]);
                        gl[n] = fma2(hv.y, w1l, gl[n]); gh[n] = fma2(hv.y, w1h, gh[n]);
                    }
                }

                ull ctxl = 0ull, ctxh = 0ull, st0l = 0ull, st0h = 0ull, st8l = 0ull, st8h = 0ull;
                #pragma unroll
                for (int n = 0; n < 9; ++n) {
                    ull al = relu2(gl[n]);
                    ull ah = relu2(gh[n]);
                    ctxl = add2(ctxl, al); ctxh = add2(ctxh, ah);
                    if (n == 0) { st0l = al; st0h = ah; }
                    if (n == 8) { st8l = al; st8h = ah; }
                }

                ull* cb = &ws.comb[pi * 192];
                cb[lane]       = st0l; cb[32 + lane]  = st0h;
                cb[64 + lane]  = st8l; cb[96 + lane]  = st8h;
                cb[128 + lane] = ctxl; cb[160 + lane] = ctxh;
            }
        }
        __syncwarp();

        // ---- S7: FC head, batched over GB pairs (fc1 via 2 LDS.128/iter) ----
        ull zc[GB][2], q0a[GB][2], q1a[GB][2];
        {
            const ull fbl = dup2(cFB[lane]);
            const ull fbh = dup2(cFB[lane + 32]);
            #pragma unroll
            for (int pq = 0; pq < GB; ++pq) {
                zc[pq][0] = 0ull; zc[pq][1] = 0ull;
                q0a[pq][0] = fbl; q0a[pq][1] = fbh;
                q1a[pq][0] = fbl; q1a[pq][1] = fbh;
            }
        }
        #pragma unroll 4
        for (int j2 = 0; j2 < 32; ++j2) {
            const float4 wsv = f4s[j2 * 32 + lane];
            const float4 wcv = f4c[j2 * 32 + lane];
            const ull s0l = dup2(wsv.x), s0h = dup2(wsv.y);
            const ull s1l = dup2(wsv.z), s1h = dup2(wsv.w);
            const ull c0l = dup2(wcv.x), c0h = dup2(wcv.y);
            const ull c1l = dup2(wcv.z), c1h = dup2(wcv.w);
            #pragma unroll
            for (int pq = 0; pq < GB; ++pq) {
                const ull* cb = &ws.comb[pq * 192];
                ulonglong2 v0 = *(const ulonglong2*)&cb[2 * j2];
                ulonglong2 v1 = *(const ulonglong2*)&cb[64 + 2 * j2];
                ulonglong2 vc = *(const ulonglong2*)&cb[128 + 2 * j2];
                q0a[pq][0] = fma2(v0.x, s0l, q0a[pq][0]); q0a[pq][1] = fma2(v0.x, s0h, q0a[pq][1]);
                q0a[pq][0] = fma2(v0.y, s1l, q0a[pq][0]); q0a[pq][1] = fma2(v0.y, s1h, q0a[pq][1]);
                q1a[pq][0] = fma2(v1.x, s0l, q1a[pq][0]); q1a[pq][1] = fma2(v1.x, s0h, q1a[pq][1]);
                q1a[pq][0] = fma2(v1.y, s1l, q1a[pq][0]); q1a[pq][1] = fma2(v1.y, s1h, q1a[pq][1]);
                zc[pq][0]  = fma2(vc.x, c0l, zc[pq][0]);  zc[pq][1]  = fma2(vc.x, c0h, zc[pq][1]);
                zc[pq][0]  = fma2(vc.y, c1l, zc[pq][0]);  zc[pq][1]  = fma2(vc.y, c1h, zc[pq][1]);
            }
        }

        // ---- epilogue: relu, fc2 dot, warp reduce, store ----
        {
            const ull f2cl = dup2(cF2[lane]);
            const ull f2ch = dup2(cF2[lane + 32]);
            #pragma unroll
            for (int pq = 0; pq < GB; ++pq) {
                const int P = base + pq;
                #pragma unroll
                for (int v = 0; v < 2; ++v) {
                    ull zl = add2(zc[pq][0], v ? q1a[pq][0] : q0a[pq][0]);
                    ull zh = add2(zc[pq][1], v ? q1a[pq][1] : q0a[pq][1]);
                    zl = relu2(zl); zh = relu2(zh);
                    ull qp = fma2(zl, f2cl, 0ull);
                    qp = fma2(zh, f2ch, qp);
                    float qa, qb; unpack2(qp, qa, qb);
                    #pragma unroll
                    for (int off = 16; off; off >>= 1) {
                        qa += __shfl_xor_sync(FULLM, qa, off);
                        qb += __shfl_xor_sync(FULLM, qb, off);
                    }
                    if (lane == 0 && P < NPAIRS) {
                        out[4 * P + v]     = qa + fc2bias;
                        out[4 * P + 2 + v] = qb + fc2bias;
                    }
                }
            }
        }

        cur = nxt;
    }

    // final-ticket warp resets the counter for the next (graph-replayed) launch.
    // Total draws are exactly NBATCH+TOTW (atomic total order), so the warp that
    // drew value NBATCH+TOTW-1 executes this strictly after every other draw.
    if (lane == 0 && cur == NBATCH + TOTW - 1) atomicExch(&g_ctr, 0);
}

extern "C" void kernel_launch(void* const* d_in, const int* in_sizes, int n_in,
                              void* d_out, int out_size) {
    const float* x    = (const float*)d_in[0];
    const int*   ei   = (const int*)  d_in[1];
    const float* W1   = (const float*)d_in[3];
    const float* b1   = (const float*)d_in[4];
    const float* W2   = (const float*)d_in[5];
    const float* b2   = (const float*)d_in[6];
    const float* fc1w = (const float*)d_in[7];
    const float* fc1b = (const float*)d_in[8];
    const float* fc2w = (const float*)d_in[9];
    const float* fc2b = (const float*)d_in[10];

    const size_t shmem = OFF_WS + sizeof(WS) * WARPS;
    cudaFuncSetAttribute(gqn_kernel, cudaFuncAttributeMaxDynamicSharedMemorySize, (int)shmem);
    gqn_kernel<<<GRID, THREADS, shmem>>>(x, ei, ei + NEDGES,
                                         W1, b1, W2, b2, fc1w, fc1b, fc2w, fc2b,
                                         (float*)d_out);
}

// round 14
// speedup vs baseline: 1.2327x; 1.1599x over previous
#include <cuda_runtime.h>
#include <cstdint>

typedef unsigned long long ull;

#define NPG 9
#define EPG 36
#define NGRAPHS 100000
#define NPAIRS (NGRAPHS / 2)
#define NEDGES (NGRAPHS * EPG)
#define WARPS 16
#define THREADS (WARPS * 32)
#define GB 3                 // graph-PAIRS per warp batch
#define NBATCH ((NPAIRS + GB - 1) / GB)   // 16667 (last batch partial)
#define GRID 152
#define TOTW (GRID * WARPS)
#define FULLM 0xffffffffu

// ---- packed f32x2 helpers ----
__device__ __forceinline__ ull pack2(float a, float b) {
    ull r; asm("mov.b64 %0, {%1, %2};" : "=l"(r) : "f"(a), "f"(b)); return r;
}
__device__ __forceinline__ void unpack2(ull v, float& a, float& b) {
    asm("mov.b64 {%0, %1}, %2;" : "=f"(a), "=f"(b) : "l"(v));
}
__device__ __forceinline__ ull fma2(ull a, ull b, ull c) {
    ull d; asm("fma.rn.f32x2 %0, %1, %2, %3;" : "=l"(d) : "l"(a), "l"(b), "l"(c)); return d;
}
__device__ __forceinline__ ull add2(ull a, ull b) {
    ull d; asm("add.rn.f32x2 %0, %1, %2;" : "=l"(d) : "l"(a), "l"(b)); return d;
}
__device__ __forceinline__ ull dup2(float a) { return pack2(a, a); }
__device__ __forceinline__ ull relu2(ull v) {
    float a, b; unpack2(v, a, b);
    return pack2(fmaxf(a, 0.f), fmaxf(b, 0.f));
}

// shared layout offsets (bytes) — W1X is 2048 B (8*32 float2)
#define OFF_FC1S  0        // [32][32] float4 interleaved station rows  16384 B
#define OFF_FC1C  16384    // [32][32] float4 interleaved ctx rows(/9)  16384 B
#define OFF_W2X   32768    // [16][32] float4 interleaved                8192 B
#define OFF_W1X   40960    // [8][32]  float2 interleaved                2048 B
#define OFF_B1    43008    // 32 f32                                      128 B
#define OFF_B2    43136    // 64 f32                                      256 B
#define OFF_FB    43392    // 64 f32 (fc1b)                               256 B
#define OFF_F2    43648    // 64 f32 (fc2w)                               256 B
#define OFF_WS    43904

// per-warp scratch; all f32x2 values interleaved as (graph0, graph1) pairs
struct __align__(16) WS {
    ull   Xi[144];        // X pair [n][k]                1152 B
    ull   Apair[90];      // A pair [n][s], stride 10      720 B
    ull   H1i[288];       // H1 pair [n][c]               2304 B
    ull   comb[GB * 192]; // st0/st8/ctx pairs            4608 B
};                        // 8784 B

__device__ int g_ctr;     // zero-initialized; reset by final-ticket warp each run

__global__ void __launch_bounds__(THREADS, 1) gqn_kernel(
    const float* __restrict__ x,
    const int*   __restrict__ esrc, const int* __restrict__ edst,
    const float* __restrict__ W1,  const float* __restrict__ b1,
    const float* __restrict__ W2,  const float* __restrict__ b2,
    const float* __restrict__ fc1w, const float* __restrict__ fc1b,
    const float* __restrict__ fc2w, const float* __restrict__ fc2b,
    float* __restrict__ out)
{
    extern __shared__ char smem[];
    float4* f4s = (float4*)(smem + OFF_FC1S);
    float4* f4c = (float4*)(smem + OFF_FC1C);
    float4* w2v = (float4*)(smem + OFF_W2X);
    float2* w1v = (float2*)(smem + OFF_W1X);
    float* cB1  = (float*)(smem + OFF_B1);
    float* cB2  = (float*)(smem + OFF_B2);
    float* cFB  = (float*)(smem + OFF_FB);
    float* cF2  = (float*)(smem + OFF_F2);
    WS* wsAll   = (WS*)(smem + OFF_WS);

    const int tid = threadIdx.x, warp = tid >> 5, lane = tid & 31;

    // ---- build interleaved weight layouts (one LDS.128 per lane per iter) ----
    const float NINTH = 1.f / 9.f;
    for (int i = tid; i < 32 * 32; i += THREADS) {   // i = j2*32 + lane
        const int j2 = i >> 5, ln = i & 31;
        const int r0 = 2 * j2, r1 = 2 * j2 + 1;
        float4 v;
        v.x = fc1w[r0 * 64 + ln];      v.y = fc1w[r0 * 64 + 32 + ln];
        v.z = fc1w[r1 * 64 + ln];      v.w = fc1w[r1 * 64 + 32 + ln];
        f4s[i] = v;
        // ctx rows pre-scaled by 1/9 (mean-pool folded into weights)
        v.x = fc1w[(64 + r0) * 64 + ln] * NINTH; v.y = fc1w[(64 + r0) * 64 + 32 + ln] * NINTH;
        v.z = fc1w[(64 + r1) * 64 + ln] * NINTH; v.w = fc1w[(64 + r1) * 64 + 32 + ln] * NINTH;
        f4c[i] = v;
    }
    for (int i = tid; i < 16 * 32; i += THREADS) {   // i = k2*32 + lane
        const int k2 = i >> 5, ln = i & 31;
        float4 v;
        v.x = W2[(2 * k2) * 64 + ln];     v.y = W2[(2 * k2) * 64 + 32 + ln];
        v.z = W2[(2 * k2 + 1) * 64 + ln]; v.w = W2[(2 * k2 + 1) * 64 + 32 + ln];
        w2v[i] = v;
    }
    for (int i = tid; i < 8 * 32; i += THREADS) {
        const int k2 = i >> 5, ln = i & 31;
        float2 v;
        v.x = W1[(2 * k2) * 32 + ln]; v.y = W1[(2 * k2 + 1) * 32 + ln];
        w1v[i] = v;
    }
    if (tid < 32)                    cB1[tid] = b1[tid];
    else if (tid < 96)               cB2[tid - 32] = b2[tid - 32];
    else if (tid < 160)              cFB[tid - 96] = fc1b[tid - 96];
    else if (tid < 224)              cF2[tid - 160] = fc2w[tid - 160];

    const float fc2bias = fc2b[0];

    WS& ws = wsAll[warp];
    __syncthreads();

    // ---- grab first batch ----
    int cur = 0;
    if (lane == 0) cur = atomicAdd(&g_ctr, 1);
    cur = __shfl_sync(FULLM, cur, 0);

    // ---- prefetch edges for first pair of first batch ----
    int ps0, ps1, ps2 = 0, pd0, pd1, pd2 = 0;
    {
        int pf = (cur < NBATCH) ? cur * GB : 0;
        const int* eb = esrc + (size_t)pf * 72;
        const int* db = edst + (size_t)pf * 72;
        ps0 = eb[lane]; ps1 = eb[32 + lane];
        pd0 = db[lane]; pd1 = db[32 + lane];
        if (lane < 8) { ps2 = eb[64 + lane]; pd2 = db[64 + lane]; }
    }

    while (cur < NBATCH) {
        // grab next batch early; latency hidden under batch work
        int nxt = 0;
        if (lane == 0) nxt = atomicAdd(&g_ctr, 1);
        nxt = __shfl_sync(FULLM, nxt, 0);

        const int base = cur * GB;

        #pragma unroll 1
        for (int pi = 0; pi < GB; ++pi) {
            const int p = base + pi;
            if (p >= NPAIRS) break;

            // ---- issue X LDGs for this pair (consumed much later) ----
            const float4* xv = (const float4*)(x + (size_t)p * 288);
            float4 xa = xv[lane], xb = xv[36 + lane];
            float4 xc, xd;
            if (lane < 4) { xc = xv[32 + lane]; xd = xv[68 + lane]; }

            // ---- consume prefetched edges; prefetch next pair's edges ----
            const int cs0 = ps0, cs1 = ps1, cs2 = ps2;
            const int cd0 = pd0, cd1 = pd1, cd2 = pd2;
            {
                int np;
                if (pi == GB - 1) np = (nxt < NBATCH) ? nxt * GB : 0;
                else              np = (p + 1 < NPAIRS) ? p + 1 : ((nxt < NBATCH) ? nxt * GB : 0);
                const int* eb = esrc + (size_t)np * 72;
                const int* db = edst + (size_t)np * 72;
                ps0 = eb[lane]; ps1 = eb[32 + lane];
                pd0 = db[lane]; pd1 = db[32 + lane];
                if (lane < 8) { ps2 = eb[64 + lane]; pd2 = db[64 + lane]; }
            }

            // ---- S2a: register-only adjacency math (ballots, norms, matches) ----
            const int b0 = p * 18;              // node base of graph 2p
            const int sA = cs0 - b0, dA = cd0 - b0;
            const int obB = (lane < 4) ? 0 : 9;
            const int sB = cs1 - (b0 + obB);
            const int dB = cd1 - (b0 + obB);
            const int sC = (lane < 8) ? (cs2 - (b0 + 9)) : 15;
            const int dC = (lane < 8) ? (cd2 - (b0 + 9)) : 15;

            int myDeg = 1;                       // self-loop
            #pragma unroll
            for (int n = 0; n < 9; ++n) {
                unsigned bA = __ballot_sync(FULLM, dA == n);
                unsigned bB = __ballot_sync(FULLM, dB == n);
                unsigned bC = __ballot_sync(FULLM, dC == n);
                int c0 = __popc(bA) + __popc(bB & 0xFu);
                int c1 = __popc(bB & ~0xFu) + __popc(bC);
                if ((int)lane == n)      myDeg += c0;
                if ((int)lane == 16 + n) myDeg += c1;
            }
            const float di  = rsqrtf((float)myDeg);   // lanes 0-8: g0, 16-24: g1
            const float di2 = di * di;

            const float nA = __shfl_sync(FULLM, di, sA) * __shfl_sync(FULLM, di, dA);
            const int ob16 = (lane < 4) ? 0 : 16;
            const float nB = __shfl_sync(FULLM, di, sB + ob16) * __shfl_sync(FULLM, di, dB + ob16);
            const float nC = __shfl_sync(FULLM, di, sC + 16) * __shfl_sync(FULLM, di, dC + 16);

            const unsigned mA = __match_any_sync(FULLM, dA * 16 + sA);
            const unsigned mB = __match_any_sync(FULLM, ob16 * 256 + dB * 16 + sB);
            const unsigned kC = (lane < 8) ? (unsigned)(dC * 16 + sC) : (4096u + lane);
            const unsigned mC = __match_any_sync(FULLM, kC);

            // ---- S2b: zero Apair with diagonal (di2) folded in ----
            {
                // region1: ulls 2*lane, 2*lane+1; diag ulls 11n (n<=5) here
                const int cA1 = 2 * lane, cB1x = cA1 + 1;
                const int nA1 = cA1 / 11, nB1 = cB1x / 11;
                const bool dgA = (nA1 * 11 == cA1) && (cA1 <= 55);
                const bool dgB = (nB1 * 11 == cB1x) && (cB1x <= 55);
                int nn = dgB ? nB1 : nA1; if (nn > 8) nn = 8;
                float va = __shfl_sync(FULLM, di2, nn);
                float vb = __shfl_sync(FULLM, di2, 16 + nn);
                ull dv = pack2(va, vb);
                ulonglong2 z;
                z.x = dgA ? dv : 0ull;
                z.y = dgB ? dv : 0ull;
                *(ulonglong2*)&ws.Apair[2 * lane] = z;

                // region2: ulls 64+2*lane (lane<13); diag ulls 66,77,88 (n=6,7,8)
                const int cC1 = 64 + 2 * lane, cD1 = cC1 + 1;
                const int nC1 = cC1 / 11, nD1 = cD1 / 11;
                const bool dgC = (nC1 * 11 == cC1) && (cC1 >= 66) && (cC1 <= 88);
                const bool dgD = (nD1 * 11 == cD1) && (cD1 >= 66) && (cD1 <= 88);
                int nn2 = dgD ? nD1 : nC1; if (nn2 > 8) nn2 = 8; if (nn2 < 0) nn2 = 0;
                float vc = __shfl_sync(FULLM, di2, nn2);
                float vd = __shfl_sync(FULLM, di2, 16 + nn2);
                ull dv2 = pack2(vc, vd);
                if (lane < 13) {
                    ulonglong2 z2;
                    z2.x = dgC ? dv2 : 0ull;
                    z2.y = dgD ? dv2 : 0ull;
                    *(ulonglong2*)&ws.Apair[64 + 2 * lane] = z2;
                }
            }
            __syncwarp();   // zeros+diag visible

            // ---- S2c: phase 1 leader adds (slots A and C) ----
            if ((int)lane == __ffs(mA) - 1) {
                float* sl = (float*)&ws.Apair[dA * 10 + sA];
                sl[0] += (float)__popc(mA) * nA;
            }
            if (lane < 8 && (int)lane == __ffs(mC) - 1) {
                float* sl = (float*)&ws.Apair[dC * 10 + sC];
                sl[1] += (float)__popc(mC) * nC;
            }
            __syncwarp();

            // ---- S2d: phase 2 leader adds (slot B) + S1b Xi stores ----
            if ((int)lane == __ffs(mB) - 1) {
                float* sl = (float*)&ws.Apair[dB * 10 + sB];
                sl[(lane < 4) ? 0 : 1] += (float)__popc(mB) * nB;
            }
            {
                ulonglong2 u0 = { pack2(xa.x, xb.x), pack2(xa.y, xb.y) };
                ulonglong2 u1 = { pack2(xa.z, xb.z), pack2(xa.w, xb.w) };
                *(ulonglong2*)&ws.Xi[4 * lane]     = u0;
                *(ulonglong2*)&ws.Xi[4 * lane + 2] = u1;
                if (lane < 4) {
                    ulonglong2 v0 = { pack2(xc.x, xd.x), pack2(xc.y, xd.y) };
                    ulonglong2 v1 = { pack2(xc.z, xd.z), pack2(xc.w, xd.w) };
                    *(ulonglong2*)&ws.Xi[128 + 4 * lane] = v0;
                    *(ulonglong2*)&ws.Xi[130 + 4 * lane] = v1;
                }
            }
            __syncwarp();

            // ---- S3: Y = X @ W1 (k-outer, W1 via one LDS.64/iter) ----
            ull y[9];
            #pragma unroll
            for (int n = 0; n < 9; ++n) y[n] = 0ull;
            #pragma unroll
            for (int k2 = 0; k2 < 8; ++k2) {
                const float2 wv = w1v[k2 * 32 + lane];
                const ull w0 = dup2(wv.x);
                const ull w1 = dup2(wv.y);
                #pragma unroll
                for (int n = 0; n < 9; ++n) {
                    ulonglong2 xp = *(const ulonglong2*)&ws.Xi[n * 16 + 2 * k2];
                    y[n] = fma2(xp.x, w0, y[n]);
                    y[n] = fma2(xp.y, w1, y[n]);
                }
            }

            // ---- S4: H1 = relu(A@Y + b1), staged to shared ----
            {
                const ull b1d = dup2(cB1[lane]);
                #pragma unroll
                for (int n = 0; n < 9; ++n) {
                    const ulonglong2* ar = (const ulonglong2*)&ws.Apair[n * 10];
                    ull acc = b1d;
                    #pragma unroll
                    for (int sp = 0; sp < 4; ++sp) {
                        ulonglong2 av = ar[sp];
                        acc = fma2(av.x, y[2 * sp],     acc);
                        acc = fma2(av.y, y[2 * sp + 1], acc);
                    }
                    acc = fma2(ws.Apair[n * 10 + 8], y[8], acc);
                    ws.H1i[n * 32 + lane] = relu2(acc);
                }
            }
            __syncwarp();

            // ---- S5: G = H1 @ W2 (W2 via one LDS.128/iter) ----
            ull gl[9], gh[9];
            #pragma unroll
            for (int n = 0; n < 9; ++n) { gl[n] = 0ull; gh[n] = 0ull; }
            #pragma unroll
            for (int k2 = 0; k2 < 16; ++k2) {
                const float4 wv = w2v[k2 * 32 + lane];
                const ull w0l = dup2(wv.x);
                const ull w0h = dup2(wv.y);
                const ull w1l = dup2(wv.z);
                const ull w1h = dup2(wv.w);
                #pragma unroll
                for (int n = 0; n < 9; ++n) {
                    ulonglong2 hv = *(const ulonglong2*)&ws.H1i[n * 32 + 2 * k2];
                    gl[n] = fma2(hv.x, w0l, gl[n]); gh[n] = fma2(hv.x, w0h, gh[n]);
                    gl[n] = fma2(hv.y, w1l, gl[n]); gh[n] = fma2(hv.y, w1h, gh[n]);
                }
            }

            // ---- S6: H2 = relu(A@G + b2); ctx SUM (1/9 folded into fc1c) + stations ----
            {
                const ull b2dl = dup2(cB2[lane]);
                const ull b2dh = dup2(cB2[lane + 32]);
                ull ctxl = 0ull, ctxh = 0ull, st0l = 0ull, st0h = 0ull, st8l = 0ull, st8h = 0ull;
                #pragma unroll
                for (int n = 0; n < 9; ++n) {
                    const ulonglong2* ar = (const ulonglong2*)&ws.Apair[n * 10];
                    ull al = b2dl, ah = b2dh;
                    #pragma unroll
                    for (int sp = 0; sp < 4; ++sp) {
                        ulonglong2 av = ar[sp];
                        al = fma2(av.x, gl[2 * sp],     al); ah = fma2(av.x, gh[2 * sp],     ah);
                        al = fma2(av.y, gl[2 * sp + 1], al); ah = fma2(av.y, gh[2 * sp + 1], ah);
                    }
                    const ull av8 = ws.Apair[n * 10 + 8];
                    al = fma2(av8, gl[8], al); ah = fma2(av8, gh[8], ah);
                    al = relu2(al); ah = relu2(ah);
                    ctxl = add2(ctxl, al); ctxh = add2(ctxh, ah);
                    if (n == 0) { st0l = al; st0h = ah; }
                    if (n == 8) { st8l = al; st8h = ah; }
                }

                ull* cb = &ws.comb[pi * 192];
                cb[lane]       = st0l; cb[32 + lane]  = st0h;
                cb[64 + lane]  = st8l; cb[96 + lane]  = st8h;
                cb[128 + lane] = ctxl; cb[160 + lane] = ctxh;
            }
        }
        __syncwarp();

        // ---- S7: FC head, batched over GB pairs (fc1 via 2 LDS.128/iter) ----
        ull zc[GB][2], q0a[GB][2], q1a[GB][2];
        {
            const ull fbl = dup2(cFB[lane]);
            const ull fbh = dup2(cFB[lane + 32]);
            #pragma unroll
            for (int pq = 0; pq < GB; ++pq) {
                zc[pq][0] = 0ull; zc[pq][1] = 0ull;
                q0a[pq][0] = fbl; q0a[pq][1] = fbh;
                q1a[pq][0] = fbl; q1a[pq][1] = fbh;
            }
        }
        #pragma unroll 4
        for (int j2 = 0; j2 < 32; ++j2) {
            const float4 wsv = f4s[j2 * 32 + lane];
            const float4 wcv = f4c[j2 * 32 + lane];
            const ull s0l = dup2(wsv.x), s0h = dup2(wsv.y);
            const ull s1l = dup2(wsv.z), s1h = dup2(wsv.w);
            const ull c0l = dup2(wcv.x), c0h = dup2(wcv.y);
            const ull c1l = dup2(wcv.z), c1h = dup2(wcv.w);
            #pragma unroll
            for (int pq = 0; pq < GB; ++pq) {
                const ull* cb = &ws.comb[pq * 192];
                ulonglong2 v0 = *(const ulonglong2*)&cb[2 * j2];
                ulonglong2 v1 = *(const ulonglong2*)&cb[64 + 2 * j2];
                ulonglong2 vc = *(const ulonglong2*)&cb[128 + 2 * j2];
                q0a[pq][0] = fma2(v0.x, s0l, q0a[pq][0]); q0a[pq][1] = fma2(v0.x, s0h, q0a[pq][1]);
                q0a[pq][0] = fma2(v0.y, s1l, q0a[pq][0]); q0a[pq][1] = fma2(v0.y, s1h, q0a[pq][1]);
                q1a[pq][0] = fma2(v1.x, s0l, q1a[pq][0]); q1a[pq][1] = fma2(v1.x, s0h, q1a[pq][1]);
                q1a[pq][0] = fma2(v1.y, s1l, q1a[pq][0]); q1a[pq][1] = fma2(v1.y, s1h, q1a[pq][1]);
                zc[pq][0]  = fma2(vc.x, c0l, zc[pq][0]);  zc[pq][1]  = fma2(vc.x, c0h, zc[pq][1]);
                zc[pq][0]  = fma2(vc.y, c1l, zc[pq][0]);  zc[pq][1]  = fma2(vc.y, c1h, zc[pq][1]);
            }
        }

        // ---- epilogue: relu, fc2 dot, warp reduce, store ----
        {
            const ull f2cl = dup2(cF2[lane]);
            const ull f2ch = dup2(cF2[lane + 32]);
            #pragma unroll
            for (int pq = 0; pq < GB; ++pq) {
                const int P = base + pq;
                #pragma unroll
                for (int v = 0; v < 2; ++v) {
                    ull zl = add2(zc[pq][0], v ? q1a[pq][0] : q0a[pq][0]);
                    ull zh = add2(zc[pq][1], v ? q1a[pq][1] : q0a[pq][1]);
                    zl = relu2(zl); zh = relu2(zh);
                    ull qp = fma2(zl, f2cl, 0ull);
                    qp = fma2(zh, f2ch, qp);
                    float qa, qb; unpack2(qp, qa, qb);
                    #pragma unroll
                    for (int off = 16; off; off >>= 1) {
                        qa += __shfl_xor_sync(FULLM, qa, off);
                        qb += __shfl_xor_sync(FULLM, qb, off);
                    }
                    if (lane == 0 && P < NPAIRS) {
                        out[4 * P + v]     = qa + fc2bias;
                        out[4 * P + 2 + v] = qb + fc2bias;
                    }
                }
            }
        }

        cur = nxt;
    }

    // final-ticket warp resets the counter for the next (graph-replayed) launch.
    // Total draws are exactly NBATCH+TOTW (atomic total order), so the warp that
    // drew value NBATCH+TOTW-1 executes this strictly after every other draw.
    if (lane == 0 && cur == NBATCH + TOTW - 1) atomicExch(&g_ctr, 0);
}

extern "C" void kernel_launch(void* const* d_in, const int* in_sizes, int n_in,
                              void* d_out, int out_size) {
    const float* x    = (const float*)d_in[0];
    const int*   ei   = (const int*)  d_in[1];
    const float* W1   = (const float*)d_in[3];
    const float* b1   = (const float*)d_in[4];
    const float* W2   = (const float*)d_in[5];
    const float* b2   = (const float*)d_in[6];
    const float* fc1w = (const float*)d_in[7];
    const float* fc1b = (const float*)d_in[8];
    const float* fc2w = (const float*)d_in[9];
    const float* fc2b = (const float*)d_in[10];

    const size_t shmem = OFF_WS + sizeof(WS) * WARPS;
    cudaFuncSetAttribute(gqn_kernel, cudaFuncAttributeMaxDynamicSharedMemorySize, (int)shmem);
    gqn_kernel<<<GRID, THREADS, shmem>>>(x, ei, ei + NEDGES,
                                         W1, b1, W2, b2, fc1w, fc1b, fc2w, fc2b,
                                         (float*)d_out);
}

// round 15
// speedup vs baseline: 1.2868x; 1.0438x over previous
#include <cuda_runtime.h>
#include <cstdint>

typedef unsigned long long ull;

#define NPG 9
#define EPG 36
#define NGRAPHS 100000
#define NPAIRS (NGRAPHS / 2)
#define NEDGES (NGRAPHS * EPG)
#define WARPS 16
#define THREADS (WARPS * 32)
#define GB 3                 // graph-PAIRS per warp batch
#define NBATCH ((NPAIRS + GB - 1) / GB)   // 16667 (last batch partial)
#define GRID 152
#define TOTW (GRID * WARPS)
#define FULLM 0xffffffffu

// ---- packed f32x2 helpers ----
__device__ __forceinline__ ull pack2(float a, float b) {
    ull r; asm("mov.b64 %0, {%1, %2};" : "=l"(r) : "f"(a), "f"(b)); return r;
}
__device__ __forceinline__ void unpack2(ull v, float& a, float& b) {
    asm("mov.b64 {%0, %1}, %2;" : "=f"(a), "=f"(b) : "l"(v));
}
__device__ __forceinline__ ull fma2(ull a, ull b, ull c) {
    ull d; asm("fma.rn.f32x2 %0, %1, %2, %3;" : "=l"(d) : "l"(a), "l"(b), "l"(c)); return d;
}
__device__ __forceinline__ ull add2(ull a, ull b) {
    ull d; asm("add.rn.f32x2 %0, %1, %2;" : "=l"(d) : "l"(a), "l"(b)); return d;
}
__device__ __forceinline__ ull dup2(float a) { return pack2(a, a); }
__device__ __forceinline__ ull relu2(ull v) {
    float a, b; unpack2(v, a, b);
    return pack2(fmaxf(a, 0.f), fmaxf(b, 0.f));
}

// shared layout offsets (bytes) — W1X is 2048 B (8*32 float2)
#define OFF_FC1S  0        // [32][32] float4 interleaved station rows  16384 B
#define OFF_FC1C  16384    // [32][32] float4 interleaved ctx rows(/9)  16384 B
#define OFF_W2X   32768    // [16][32] float4 interleaved                8192 B
#define OFF_W1X   40960    // [8][32]  float2 interleaved                2048 B
#define OFF_B1    43008    // 32 f32                                      128 B
#define OFF_B2    43136    // 64 f32                                      256 B
#define OFF_FB    43392    // 64 f32 (fc1b)                               256 B
#define OFF_F2    43648    // 64 f32 (fc2w)                               256 B
#define OFF_WS    43904

// per-warp scratch; all f32x2 values interleaved as (graph0, graph1) pairs
// comb layout per pair: [ (st0(c),st8(c)) pairs for c=0..63 ][ ctxl x32 ][ ctxh x32 ]
struct __align__(16) WS {
    ull   Xi[144];        // X pair [n][k]                1152 B
    ull   Apair[90];      // A pair [n][s], stride 10      720 B
    ull   H1i[288];       // H1 pair [n][c]               2304 B
    ull   comb[GB * 192]; // packed head inputs           4608 B
};                        // 8784 B

__device__ int g_ctr;     // zero-initialized; reset by final-ticket warp each run

__global__ void __launch_bounds__(THREADS, 1) gqn_kernel(
    const float* __restrict__ x,
    const int*   __restrict__ esrc, const int* __restrict__ edst,
    const float* __restrict__ W1,  const float* __restrict__ b1,
    const float* __restrict__ W2,  const float* __restrict__ b2,
    const float* __restrict__ fc1w, const float* __restrict__ fc1b,
    const float* __restrict__ fc2w, const float* __restrict__ fc2b,
    float* __restrict__ out)
{
    extern __shared__ char smem[];
    float4* f4s = (float4*)(smem + OFF_FC1S);
    float4* f4c = (float4*)(smem + OFF_FC1C);
    float4* w2v = (float4*)(smem + OFF_W2X);
    float2* w1v = (float2*)(smem + OFF_W1X);
    float* cB1  = (float*)(smem + OFF_B1);
    float* cB2  = (float*)(smem + OFF_B2);
    float* cFB  = (float*)(smem + OFF_FB);
    float* cF2  = (float*)(smem + OFF_F2);
    WS* wsAll   = (WS*)(smem + OFF_WS);

    const int tid = threadIdx.x, warp = tid >> 5, lane = tid & 31;

    // ---- build interleaved weight layouts (one LDS.128 per lane per iter) ----
    const float NINTH = 1.f / 9.f;
    for (int i = tid; i < 32 * 32; i += THREADS) {   // i = j2*32 + lane
        const int j2 = i >> 5, ln = i & 31;
        const int r0 = 2 * j2, r1 = 2 * j2 + 1;
        float4 v;
        v.x = fc1w[r0 * 64 + ln];      v.y = fc1w[r0 * 64 + 32 + ln];
        v.z = fc1w[r1 * 64 + ln];      v.w = fc1w[r1 * 64 + 32 + ln];
        f4s[i] = v;
        // ctx rows pre-scaled by 1/9 (mean-pool folded into weights)
        v.x = fc1w[(64 + r0) * 64 + ln] * NINTH; v.y = fc1w[(64 + r0) * 64 + 32 + ln] * NINTH;
        v.z = fc1w[(64 + r1) * 64 + ln] * NINTH; v.w = fc1w[(64 + r1) * 64 + 32 + ln] * NINTH;
        f4c[i] = v;
    }
    for (int i = tid; i < 16 * 32; i += THREADS) {   // i = k2*32 + lane
        const int k2 = i >> 5, ln = i & 31;
        float4 v;
        v.x = W2[(2 * k2) * 64 + ln];     v.y = W2[(2 * k2) * 64 + 32 + ln];
        v.z = W2[(2 * k2 + 1) * 64 + ln]; v.w = W2[(2 * k2 + 1) * 64 + 32 + ln];
        w2v[i] = v;
    }
    for (int i = tid; i < 8 * 32; i += THREADS) {
        const int k2 = i >> 5, ln = i & 31;
        float2 v;
        v.x = W1[(2 * k2) * 32 + ln]; v.y = W1[(2 * k2 + 1) * 32 + ln];
        w1v[i] = v;
    }
    if (tid < 32)                    cB1[tid] = b1[tid];
    else if (tid < 96)               cB2[tid - 32] = b2[tid - 32];
    else if (tid < 160)              cFB[tid - 96] = fc1b[tid - 96];
    else if (tid < 224)              cF2[tid - 160] = fc2w[tid - 160];

    const float fc2bias = fc2b[0];

    WS& ws = wsAll[warp];
    __syncthreads();

    // ---- grab first batch ----
    int cur = 0;
    if (lane == 0) cur = atomicAdd(&g_ctr, 1);
    cur = __shfl_sync(FULLM, cur, 0);

    // ---- prefetch edges for first pair of first batch ----
    int ps0, ps1, ps2 = 0, pd0, pd1, pd2 = 0;
    {
        int pf = (cur < NBATCH) ? cur * GB : 0;
        const int* eb = esrc + (size_t)pf * 72;
        const int* db = edst + (size_t)pf * 72;
        ps0 = eb[lane]; ps1 = eb[32 + lane];
        pd0 = db[lane]; pd1 = db[32 + lane];
        if (lane < 8) { ps2 = eb[64 + lane]; pd2 = db[64 + lane]; }
    }

    while (cur < NBATCH) {
        // grab next batch early; latency hidden under batch work
        int nxt = 0;
        if (lane == 0) nxt = atomicAdd(&g_ctr, 1);
        nxt = __shfl_sync(FULLM, nxt, 0);

        const int base = cur * GB;

        #pragma unroll 1
        for (int pi = 0; pi < GB; ++pi) {
            const int p = base + pi;
            if (p >= NPAIRS) break;

            // ---- issue X LDGs for this pair (consumed much later) ----
            const float4* xv = (const float4*)(x + (size_t)p * 288);
            float4 xa = xv[lane], xb = xv[36 + lane];
            float4 xc, xd;
            if (lane < 4) { xc = xv[32 + lane]; xd = xv[68 + lane]; }

            // ---- consume prefetched edges; prefetch next pair's edges ----
            const int cs0 = ps0, cs1 = ps1, cs2 = ps2;
            const int cd0 = pd0, cd1 = pd1, cd2 = pd2;
            {
                int np;
                if (pi == GB - 1) np = (nxt < NBATCH) ? nxt * GB : 0;
                else              np = (p + 1 < NPAIRS) ? p + 1 : ((nxt < NBATCH) ? nxt * GB : 0);
                const int* eb = esrc + (size_t)np * 72;
                const int* db = edst + (size_t)np * 72;
                ps0 = eb[lane]; ps1 = eb[32 + lane];
                pd0 = db[lane]; pd1 = db[32 + lane];
                if (lane < 8) { ps2 = eb[64 + lane]; pd2 = db[64 + lane]; }
            }

            // ---- zero Apair ----
            {
                ulonglong2 z2 = make_ulonglong2(0ull, 0ull);
                *(ulonglong2*)&ws.Apair[2 * lane] = z2;
                if (lane < 13) *(ulonglong2*)&ws.Apair[64 + 2 * lane] = z2;
            }

            // ---- S2: adjacency via ballots/shuffles, 72 edges in 3 slots ----
            const int b0 = p * 18;              // node base of graph 2p
            const int sA = cs0 - b0, dA = cd0 - b0;
            const int obB = (lane < 4) ? 0 : 9;
            const int sB = cs1 - (b0 + obB);
            const int dB = cd1 - (b0 + obB);
            const int sC = (lane < 8) ? (cs2 - (b0 + 9)) : 15;
            const int dC = (lane < 8) ? (cd2 - (b0 + 9)) : 15;

            int myDeg = 1;                       // self-loop
            #pragma unroll
            for (int n = 0; n < 9; ++n) {
                unsigned bA = __ballot_sync(FULLM, dA == n);
                unsigned bB = __ballot_sync(FULLM, dB == n);
                unsigned bC = __ballot_sync(FULLM, dC == n);
                int c0 = __popc(bA) + __popc(bB & 0xFu);
                int c1 = __popc(bB & ~0xFu) + __popc(bC);
                if ((int)lane == n)      myDeg += c0;
                if ((int)lane == 16 + n) myDeg += c1;
            }
            const float di  = rsqrtf((float)myDeg);   // lanes 0-8: g0, 16-24: g1
            const float di2 = di * di;

            const float nA = __shfl_sync(FULLM, di, sA) * __shfl_sync(FULLM, di, dA);
            const int ob16 = (lane < 4) ? 0 : 16;
            const float nB = __shfl_sync(FULLM, di, sB + ob16) * __shfl_sync(FULLM, di, dB + ob16);
            const float nC = __shfl_sync(FULLM, di, sC + 16) * __shfl_sync(FULLM, di, dC + 16);

            const unsigned mA = __match_any_sync(FULLM, dA * 16 + sA);
            const unsigned mB = __match_any_sync(FULLM, ob16 * 256 + dB * 16 + sB);
            const unsigned kC = (lane < 8) ? (unsigned)(dC * 16 + sC) : (4096u + lane);
            const unsigned mC = __match_any_sync(FULLM, kC);

            __syncwarp();   // zeros visible
            if ((int)lane == __ffs(mA) - 1) {
                float* sl = (float*)&ws.Apair[dA * 10 + sA];
                sl[0] += (float)__popc(mA) * nA;
            }
            if (lane < 8 && (int)lane == __ffs(mC) - 1) {
                float* sl = (float*)&ws.Apair[dC * 10 + sC];
                sl[1] += (float)__popc(mC) * nC;
            }
            __syncwarp();
            if ((int)lane == __ffs(mB) - 1) {
                float* sl = (float*)&ws.Apair[dB * 10 + sB];
                sl[(lane < 4) ? 0 : 1] += (float)__popc(mB) * nB;
            }
            __syncwarp();
            if (lane < 9)
                ((float*)&ws.Apair[lane * 10 + lane])[0] += di2;
            if (lane >= 16 && lane < 25)
                ((float*)&ws.Apair[(lane - 16) * 10 + (lane - 16)])[1] += di2;

            // ---- S1b: store X pairs (LDG data now long arrived) ----
            {
                ulonglong2 u0 = { pack2(xa.x, xb.x), pack2(xa.y, xb.y) };
                ulonglong2 u1 = { pack2(xa.z, xb.z), pack2(xa.w, xb.w) };
                *(ulonglong2*)&ws.Xi[4 * lane]     = u0;
                *(ulonglong2*)&ws.Xi[4 * lane + 2] = u1;
                if (lane < 4) {
                    ulonglong2 v0 = { pack2(xc.x, xd.x), pack2(xc.y, xd.y) };
                    ulonglong2 v1 = { pack2(xc.z, xd.z), pack2(xc.w, xd.w) };
                    *(ulonglong2*)&ws.Xi[128 + 4 * lane] = v0;
                    *(ulonglong2*)&ws.Xi[130 + 4 * lane] = v1;
                }
            }
            __syncwarp();

            // ---- S3: Y = X @ W1 (k-outer, W1 via one LDS.64/iter) ----
            ull y[9];
            #pragma unroll
            for (int n = 0; n < 9; ++n) y[n] = 0ull;
            #pragma unroll
            for (int k2 = 0; k2 < 8; ++k2) {
                const float2 wv = w1v[k2 * 32 + lane];
                const ull w0 = dup2(wv.x);
                const ull w1 = dup2(wv.y);
                #pragma unroll
                for (int n = 0; n < 9; ++n) {
                    ulonglong2 xp = *(const ulonglong2*)&ws.Xi[n * 16 + 2 * k2];
                    y[n] = fma2(xp.x, w0, y[n]);
                    y[n] = fma2(xp.y, w1, y[n]);
                }
            }

            // ---- S4: H1 = relu(A@Y + b1), staged to shared ----
            {
                const ull b1d = dup2(cB1[lane]);
                #pragma unroll
                for (int n = 0; n < 9; ++n) {
                    const ulonglong2* ar = (const ulonglong2*)&ws.Apair[n * 10];
                    ull acc = b1d;
                    #pragma unroll
                    for (int sp = 0; sp < 4; ++sp) {
                        ulonglong2 av = ar[sp];
                        acc = fma2(av.x, y[2 * sp],     acc);
                        acc = fma2(av.y, y[2 * sp + 1], acc);
                    }
                    acc = fma2(ws.Apair[n * 10 + 8], y[8], acc);
                    ws.H1i[n * 32 + lane] = relu2(acc);
                }
            }
            __syncwarp();

            // ---- S5: G = H1 @ W2 (W2 via one LDS.128/iter) ----
            ull gl[9], gh[9];
            #pragma unroll
            for (int n = 0; n < 9; ++n) { gl[n] = 0ull; gh[n] = 0ull; }
            #pragma unroll
            for (int k2 = 0; k2 < 16; ++k2) {
                const float4 wv = w2v[k2 * 32 + lane];
                const ull w0l = dup2(wv.x);
                const ull w0h = dup2(wv.y);
                const ull w1l = dup2(wv.z);
                const ull w1h = dup2(wv.w);
                #pragma unroll
                for (int n = 0; n < 9; ++n) {
                    ulonglong2 hv = *(const ulonglong2*)&ws.H1i[n * 32 + 2 * k2];
                    gl[n] = fma2(hv.x, w0l, gl[n]); gh[n] = fma2(hv.x, w0h, gh[n]);
                    gl[n] = fma2(hv.y, w1l, gl[n]); gh[n] = fma2(hv.y, w1h, gh[n]);
                }
            }

            // ---- S6: H2 = relu(A@G + b2); ctx SUM (1/9 folded into fc1c) + stations ----
            {
                const ull b2dl = dup2(cB2[lane]);
                const ull b2dh = dup2(cB2[lane + 32]);
                ull ctxl = 0ull, ctxh = 0ull, st0l = 0ull, st0h = 0ull, st8l = 0ull, st8h = 0ull;
                #pragma unroll
                for (int n = 0; n < 9; ++n) {
                    const ulonglong2* ar = (const ulonglong2*)&ws.Apair[n * 10];
                    ull al = b2dl, ah = b2dh;
                    #pragma unroll
                    for (int sp = 0; sp < 4; ++sp) {
                        ulonglong2 av = ar[sp];
                        al = fma2(av.x, gl[2 * sp],     al); ah = fma2(av.x, gh[2 * sp],     ah);
                        al = fma2(av.y, gl[2 * sp + 1], al); ah = fma2(av.y, gh[2 * sp + 1], ah);
                    }
                    const ull av8 = ws.Apair[n * 10 + 8];
                    al = fma2(av8, gl[8], al); ah = fma2(av8, gh[8], ah);
                    al = relu2(al); ah = relu2(ah);
                    ctxl = add2(ctxl, al); ctxh = add2(ctxh, ah);
                    if (n == 0) { st0l = al; st0h = ah; }
                    if (n == 8) { st8l = al; st8h = ah; }
                }

                // packed comb stores: (st0,st8) interleaved per channel
                ull* cb = &ws.comb[pi * 192];
                ulonglong2 plo = { st0l, st8l };
                ulonglong2 phi = { st0h, st8h };
                *(ulonglong2*)&cb[2 * lane]      = plo;   // channels 0..31
                *(ulonglong2*)&cb[64 + 2 * lane] = phi;   // channels 32..63
                cb[128 + lane] = ctxl; cb[160 + lane] = ctxh;
            }
        }
        __syncwarp();

        // ---- S7: FC head, batched over GB pairs (fc1 via 2 LDS.128/iter) ----
        ull zc[GB][2], q0a[GB][2], q1a[GB][2];
        {
            const ull fbl = dup2(cFB[lane]);
            const ull fbh = dup2(cFB[lane + 32]);
            #pragma unroll
            for (int pq = 0; pq < GB; ++pq) {
                zc[pq][0] = 0ull; zc[pq][1] = 0ull;
                q0a[pq][0] = fbl; q0a[pq][1] = fbh;
                q1a[pq][0] = fbl; q1a[pq][1] = fbh;
            }
        }
        #pragma unroll 4
        for (int j2 = 0; j2 < 32; ++j2) {
            const float4 wsv = f4s[j2 * 32 + lane];
            const float4 wcv = f4c[j2 * 32 + lane];
            const ull s0l = dup2(wsv.x), s0h = dup2(wsv.y);
            const ull s1l = dup2(wsv.z), s1h = dup2(wsv.w);
            const ull c0l = dup2(wcv.x), c0h = dup2(wcv.y);
            const ull c1l = dup2(wcv.z), c1h = dup2(wcv.w);
            #pragma unroll
            for (int pq = 0; pq < GB; ++pq) {
                const ull* cb = &ws.comb[pq * 192];
                ulonglong2 r0 = *(const ulonglong2*)&cb[4 * j2];       // (st0(j0), st8(j0))
                ulonglong2 r1 = *(const ulonglong2*)&cb[4 * j2 + 2];   // (st0(j1), st8(j1))
                ulonglong2 vc = *(const ulonglong2*)&cb[128 + 2 * j2]; // (ctx(j0), ctx(j1))
                q0a[pq][0] = fma2(r0.x, s0l, q0a[pq][0]); q0a[pq][1] = fma2(r0.x, s0h, q0a[pq][1]);
                q0a[pq][0] = fma2(r1.x, s1l, q0a[pq][0]); q0a[pq][1] = fma2(r1.x, s1h, q0a[pq][1]);
                q1a[pq][0] = fma2(r0.y, s0l, q1a[pq][0]); q1a[pq][1] = fma2(r0.y, s0h, q1a[pq][1]);
                q1a[pq][0] = fma2(r1.y, s1l, q1a[pq][0]); q1a[pq][1] = fma2(r1.y, s1h, q1a[pq][1]);
                zc[pq][0]  = fma2(vc.x, c0l, zc[pq][0]);  zc[pq][1]  = fma2(vc.x, c0h, zc[pq][1]);
                zc[pq][0]  = fma2(vc.y, c1l, zc[pq][0]);  zc[pq][1]  = fma2(vc.y, c1h, zc[pq][1]);
            }
        }

        // ---- epilogue: relu, fc2 dot, warp reduce, store ----
        {
            const ull f2cl = dup2(cF2[lane]);
            const ull f2ch = dup2(cF2[lane + 32]);
            #pragma unroll
            for (int pq = 0; pq < GB; ++pq) {
                const int P = base + pq;
                #pragma unroll
                for (int v = 0; v < 2; ++v) {
                    ull zl = add2(zc[pq][0], v ? q1a[pq][0] : q0a[pq][0]);
                    ull zh = add2(zc[pq][1], v ? q1a[pq][1] : q0a[pq][1]);
                    zl = relu2(zl); zh = relu2(zh);
                    ull qp = fma2(zl, f2cl, 0ull);
                    qp = fma2(zh, f2ch, qp);
                    float qa, qb; unpack2(qp, qa, qb);
                    #pragma unroll
                    for (int off = 16; off; off >>= 1) {
                        qa += __shfl_xor_sync(FULLM, qa, off);
                        qb += __shfl_xor_sync(FULLM, qb, off);
                    }
                    if (lane == 0 && P < NPAIRS) {
                        out[4 * P + v]     = qa + fc2bias;
                        out[4 * P + 2 + v] = qb + fc2bias;
                    }
                }
            }
        }

        cur = nxt;
    }

    // final-ticket warp resets the counter for the next (graph-replayed) launch.
    // Total draws are exactly NBATCH+TOTW (atomic total order), so the warp that
    // drew value NBATCH+TOTW-1 executes this strictly after every other draw.
    if (lane == 0 && cur == NBATCH + TOTW - 1) atomicExch(&g_ctr, 0);
}

extern "C" void kernel_launch(void* const* d_in, const int* in_sizes, int n_in,
                              void* d_out, int out_size) {
    const float* x    = (const float*)d_in[0];
    const int*   ei   = (const int*)  d_in[1];
    const float* W1   = (const float*)d_in[3];
    const float* b1   = (const float*)d_in[4];
    const float* W2   = (const float*)d_in[5];
    const float* b2   = (const float*)d_in[6];
    const float* fc1w = (const float*)d_in[7];
    const float* fc1b = (const float*)d_in[8];
    const float* fc2w = (const float*)d_in[9];
    const float* fc2b = (const float*)d_in[10];

    const size_t shmem = OFF_WS + sizeof(WS) * WARPS;
    cudaFuncSetAttribute(gqn_kernel, cudaFuncAttributeMaxDynamicSharedMemorySize, (int)shmem);
    gqn_kernel<<<GRID, THREADS, shmem>>>(x, ei, ei + NEDGES,
                                         W1, b1, W2, b2, fc1w, fc1b, fc2w, fc2b,
                                         (float*)d_out);
}